// round 3
// baseline (speedup 1.0000x reference)
#include <cuda_runtime.h>
#include <math.h>

// Problem constants: B=4, C=8, H=W=512
// pad = (int(sqrt(2)*512)-512)//2 + 1 = 107 ; padded = 726
#define BB 4
#define CC 8
#define HH 512
#define WW 512
#define PAD 107
#define HP 726
#define PLANE (HH * WW)
#define DEG2RAD 0.017453292519943295f

#define TILE    64          // output tile per block (64x64)
#define BOX     96          // staged source region (rows/cols)
#define SSTRIDE 97          // smem row stride (floats) - bank spreading
#define THREADS 512

// Source (unpadded, float) coordinate of output pixel (ox, oy).
// EXACTLY the same fp32 op sequence for corners and pixels so the
// corner-derived bbox bounds the per-pixel values (rotation is linear; fp
// rounding differences are < 1 ulp, covered by the 1-texel bbox margin).
__device__ __forceinline__ void src_coord(float ox, float oy,
                                          float cs, float sn,
                                          float& fx, float& fy)
{
    const float step = 2.0f / 725.0f;
    const float pxv = fmaf(ox + (float)PAD, step, -1.0f);
    const float pyv = fmaf(oy + (float)PAD, step, -1.0f);
    const float gx = pxv * cs - pyv * sn;
    const float gy = pxv * sn + pyv * cs;
    fx = ((gx + 1.0f) * (float)HP - 1.0f) * 0.5f - (float)PAD;
    fy = ((gy + 1.0f) * (float)HP - 1.0f) * 0.5f - (float)PAD;
}

__global__ __launch_bounds__(THREADS)
void diff_pair_rotate_smem(const float* __restrict__ xin,
                           const float* __restrict__ yin,
                           const float* __restrict__ angles,
                           float* __restrict__ out)
{
    __shared__ float sm[BOX * SSTRIDE];   // 37,248 B static — one plane

    const int tile = blockIdx.x;          // 0..63 (8x8 tiles)
    const int c    = blockIdx.y;          // channel
    const int b    = blockIdx.z;          // batch
    const int tx   = (tile & 7) * TILE;
    const int ty   = (tile >> 3) * TILE;

    const float rad = angles[b] * DEG2RAD;
    float sn, cs;
    sincosf(rad, &sn, &cs);

    // ---- bbox from the 4 tile corners (rotation is linear) ----
    float fx0, fy0, fx1, fy1, fx2, fy2, fx3, fy3;
    src_coord((float)tx,            (float)ty,            cs, sn, fx0, fy0);
    src_coord((float)(tx + TILE-1), (float)ty,            cs, sn, fx1, fy1);
    src_coord((float)tx,            (float)(ty + TILE-1), cs, sn, fx2, fy2);
    src_coord((float)(tx + TILE-1), (float)(ty + TILE-1), cs, sn, fx3, fy3);

    const float fxmin = fminf(fminf(fx0, fx1), fminf(fx2, fx3));
    const float fymin = fminf(fminf(fy0, fy1), fminf(fy2, fy3));

    // 1-texel safety margin below the minimum tap
    const int ox0 = (int)floorf(fxmin) - 1;
    const int oy0 = (int)floorf(fymin) - 1;
    const float fox0 = (float)ox0;
    const float foy0 = (float)oy0;

    const int tid = threadIdx.x;
    const int lx  = tid & 63;             // 0..63 within tile row
    const int lyb = tid >> 6;             // 0..7

    const size_t plane_off = ((size_t)(b * CC + c)) * PLANE;
    const float* planes[2] = { xin + plane_off, yin + plane_off };
    float* outs[2] = { out + plane_off,
                       out + (size_t)(BB * CC) * PLANE + plane_off };

    #pragma unroll
    for (int phase = 0; phase < 2; ++phase) {
        const float* __restrict__ src = planes[phase];
        float* __restrict__ dst = outs[phase];

        if (phase) __syncthreads();       // buffer reuse barrier

        // ---- stage: coalesced rows, zero-fill outside the image ----
        #pragma unroll
        for (int i = tid; i < BOX * BOX; i += THREADS) {
            const int r  = i / BOX;
            const int cl = i - r * BOX;
            const int gx = ox0 + cl;
            const int gy = oy0 + r;
            float v = 0.0f;
            if (((unsigned)gx) < (unsigned)WW && ((unsigned)gy) < (unsigned)HH) {
                v = __ldg(src + gy * WW + gx);
            }
            sm[r * SSTRIDE + cl] = v;
        }
        __syncthreads();

        // ---- sample: branch-free bilinear from smem ----
        #pragma unroll
        for (int r = 0; r < 8; ++r) {
            const int oyp = ty + lyb + r * 8;
            const int oxp = tx + lx;

            float fx, fy;
            src_coord((float)oxp, (float)oyp, cs, sn, fx, fy);

            const float x0f = floorf(fx);
            const float y0f = floorf(fy);
            const float wx1 = fx - x0f, wx0 = 1.0f - wx1;
            const float wy1 = fy - y0f, wy0 = 1.0f - wy1;

            const int sx = (int)(x0f - fox0);   // in [0, BOX-2]
            const int sy = (int)(y0f - foy0);
            const int s00 = sy * SSTRIDE + sx;

            const float w00 = wx0 * wy0;
            const float w10 = wx1 * wy0;
            const float w01 = wx0 * wy1;
            const float w11 = wx1 * wy1;

            float acc =       sm[s00]               * w00;
            acc = fmaf(sm[s00 + 1],           w10, acc);
            acc = fmaf(sm[s00 + SSTRIDE],     w01, acc);
            acc = fmaf(sm[s00 + SSTRIDE + 1], w11, acc);

            dst[oyp * WW + oxp] = acc;
        }
    }
}

extern "C" void kernel_launch(void* const* d_in, const int* in_sizes, int n_in,
                              void* d_out, int out_size)
{
    const float* x      = (const float*)d_in[0];
    const float* y      = (const float*)d_in[1];
    const float* angles = (const float*)d_in[2];
    float* out          = (float*)d_out;

    dim3 block(THREADS);
    dim3 grid(64, CC, BB);   // 8x8 tiles, 8 channels, 4 batches
    diff_pair_rotate_smem<<<grid, block>>>(x, y, angles, out);
}